// round 10
// baseline (speedup 1.0000x reference)
#include <cuda_runtime.h>
#include <math.h>

#define TOT    8192
#define NBATCH 16
#define NE     131072
#define NW     16
#define NPAD   160     // 10 unique p * 16 w = 160 (5 regs/lane)

// ---- device-global scratch (no allocations allowed) ----
__device__ float g_edata[(size_t)NE * 32];      // CSR: [0..9]=uniq ang, [10..13]=0, [14]=dcut, [15]=0, [16..31]=radial
__device__ int   g_ej[NE];                      // CSR-ordered j index per edge
__device__ int   g_cnt[TOT];
__device__ int   g_ptr[TOT + 1];
__device__ int   g_done;                        // completion counter for count_scan (self-resetting)
__device__ float g_wsum[2][(size_t)TOT * NPAD]; // double-buffered running sum of ef_orbs (unique rows)
__device__ float g_coeff[2][TOT * NW];          // double-buffered orb_coeff
__device__ float g_angef[NBATCH * 16];          // angular(ef) unique rows, padded to 16

// ---- packed f32x2 helpers (full fp32 precision, 2 FMA/instr on sm_103a) ----
__device__ __forceinline__ unsigned long long pk2(float lo, float hi) {
    unsigned long long r;
    asm("mov.b64 %0,{%1,%2};" : "=l"(r) : "f"(lo), "f"(hi));
    return r;
}
__device__ __forceinline__ void upk2(unsigned long long v, float& lo, float& hi) {
    asm("mov.b64 {%0,%1},%2;" : "=f"(lo), "=f"(hi) : "l"(v));
}
__device__ __forceinline__ unsigned long long ffma2(unsigned long long a,
                                                    unsigned long long b,
                                                    unsigned long long c) {
    unsigned long long d;
    asm("fma.rn.f32x2 %0,%1,%2,%3;" : "=l"(d) : "l"(a), "l"(b), "l"(c));
    return d;
}

// orb_coeff init + zero CSR counters + angular(ef) unique basis
__global__ void k_init(const float* __restrict__ params_p,
                       const int* __restrict__ species,
                       const float* __restrict__ ef) {
    int t = blockIdx.x * blockDim.x + threadIdx.x;
    if (t < TOT * NW) {
        int a = t >> 4, w = t & 15;
        g_coeff[0][t] = params_p[species[a] * NW + w];
    }
    if (t < TOT) g_cnt[t] = 0;
    if (t < NBATCH) {
        float x = ef[3*t], y = ef[3*t+1], z = ef[3*t+2];
        float* o = g_angef + t * 16;
        o[0]=1.f; o[1]=x; o[2]=y; o[3]=z;
        o[4]=x*x; o[5]=x*y; o[6]=x*z; o[7]=y*y; o[8]=y*z; o[9]=z*z;
        o[10]=0.f; o[11]=0.f; o[12]=0.f; o[13]=0.f; o[14]=0.f; o[15]=0.f;
    }
}

// CSR count + (last block) exclusive scan -> g_ptr; rezero counts as cursors.
__global__ void k_count_scan(const int* __restrict__ neigh) {
    int e = blockIdx.x * blockDim.x + threadIdx.x;
    if (e < NE) atomicAdd(&g_cnt[neigh[e]], 1);
    __threadfence();
    __shared__ int isLast;
    if (threadIdx.x == 0) {
        int d = atomicAdd(&g_done, 1);
        isLast = (d == (int)gridDim.x - 1);
    }
    __syncthreads();
    if (!isLast) return;

    // last block: 256 threads x 32 counts each
    __shared__ int ss[256];
    int t = threadIdx.x;
    int loc[32]; int s = 0;
    #pragma unroll
    for (int k = 0; k < 32; k++) { loc[k] = __ldcg(&g_cnt[t*32 + k]); s += loc[k]; }
    ss[t] = s; __syncthreads();
    for (int off = 1; off < 256; off <<= 1) {
        int v = ss[t];
        int add = (t >= off) ? ss[t - off] : 0;
        __syncthreads();
        ss[t] = v + add;
        __syncthreads();
    }
    int run = ss[t] - s;
    if (t == 0) { g_ptr[0] = 0; g_done = 0; }   // reset done for next graph replay
    #pragma unroll
    for (int k = 0; k < 32; k++) {
        run += loc[k];
        g_ptr[t*32 + k + 1] = run;
        g_cnt[t*32 + k] = 0;                    // cursors for k_edge
    }
}

// per-edge geometry + radial/angular (unique rows) precompute, scattered into CSR slot
__global__ void k_edge(const float* __restrict__ cart, const float* __restrict__ shifts,
                       const float* __restrict__ rs, const float* __restrict__ inta,
                       const int* __restrict__ neigh,
                       const int* __restrict__ species) {
    int e = blockIdx.x * blockDim.x + threadIdx.x;
    if (e >= NE) return;
    int i = neigh[e];
    int j = neigh[NE + e];
    float dx = cart[3*i]   - cart[3*j]   - shifts[3*e];
    float dy = cart[3*i+1] - cart[3*j+1] - shifts[3*e+1];
    float dz = cart[3*i+2] - cart[3*j+2] - shifts[3*e+2];
    float d2 = dx*dx + dy*dy + dz*dz;
    float rinv = rsqrtf(d2);
    float d = d2 * rinv;
    float ux = dx * rinv, uy = dy * rinv, uz = dz * rinv;
    float fc = 0.5f * __cosf(d * 0.6283185307179586f) + 0.5f;
    float dcut = fc * fc;
    int sp = species[j];

    float buf[32];
    // unique angular rows: 0:1, 1:x,2:y,3:z, 4:xx,5:xy,6:xz,7:yy,8:yz,9:zz (all * dcut)
    buf[0] = dcut;
    buf[1] = dcut*ux; buf[2] = dcut*uy; buf[3] = dcut*uz;
    buf[4] = buf[1]*ux; buf[5] = buf[1]*uy; buf[6] = buf[1]*uz;
    buf[7] = buf[2]*uy; buf[8] = buf[2]*uz; buf[9] = buf[3]*uz;
    buf[10]=0.f; buf[11]=0.f; buf[12]=0.f; buf[13]=0.f;
    buf[14]=dcut; buf[15]=0.f;
    #pragma unroll
    for (int w = 0; w < 16; w++) {
        float t = d - rs[sp*16 + w];
        buf[16 + w] = __expf(inta[sp*16 + w] * t * t);
    }
    int pos = g_ptr[i] + atomicAdd(&g_cnt[i], 1);   // CSR slot
    float4* dst = (float4*)(g_edata + (size_t)pos * 32);
    const float4* src = (const float4*)buf;
    #pragma unroll
    for (int q = 0; q < 8; q++) dst[q] = src[q];
    g_ej[pos] = j;
}

// Fused obtain: gather (warp-per-atom, CSR-sequential, batch-4 pipelined)
//               -> density (f32x2) -> wsum update -> MLP (f32x2).
// MODE 0: first obtain (no wsum term; wsum_next = ef_orb; MLP)
// MODE 1: middle obtain (wsum term; wsum_next = wsum_cur + ef_orb; MLP)
// MODE 2: last obtain (wsum term; density -> d_out; no wsum/MLP)
// Lane map: idx = lane + 32k (k<5): w = lane&15, pu = (lane>>4) + 2k  (pu in 0..9).
// Owner of (pu,w): lane = w + 16*(pu&1), register acc[pu>>1].
template<int MODE>
__global__ void __launch_bounds__(256, 2) k_obtain(
    const float* __restrict__ ef_para, const float* __restrict__ hyper,
    const float* __restrict__ w1, const float* __restrict__ b1,
    const float* __restrict__ w2, float* __restrict__ dens_out,
    int csel, int wsel)
{
    __shared__ float sBuf[9280];   // [0:6144) hyper; reused: W1(pair-interleaved)[0:8192) W2[8192:9216) b1[9216:9280)
    __shared__ float sT[8][64];    // tanh staging per warp
    const unsigned FULL = 0xFFFFFFFFu;
    int tid = threadIdx.x, lane = tid & 31, wid = tid >> 5;
    int a = blockIdx.x * 8 + wid;

    const float* coeff_cur = g_coeff[csel];
    const float* wsum_cur  = g_wsum[wsel];

    // stage hyper early (float4); latency hides behind gather
    for (int idx = tid; idx < 1536; idx += 256)
        ((float4*)sBuf)[idx] = ((const float4*)hyper)[idx];

    int wlo = lane & 15;
    int base = lane >> 4;
    int b = a >> 9;                    // batch = atom / 512
    float efw = ef_para[wlo];
    float acc[5];
    #pragma unroll
    for (int k = 0; k < 5; k++)
        acc[k] = g_angef[b*16 + base + 2*k] * efw;   // ef_orb0 unique rows

    int start = g_ptr[a], end = g_ptr[a + 1];
    for (int cb = start; cb < end; cb += 32) {
        int cn = min(32, end - cb);
        int jv = (cb + lane < end) ? __ldg(&g_ej[cb + lane]) : 0;
        for (int s0 = 0; s0 < cn; s0 += 4) {
            float rr[4], cc[4], wsv[4][5];
            #pragma unroll
            for (int u = 0; u < 4; u++) {
                int s = s0 + u;
                if (s < cn) {                           // warp-uniform guard
                    int jj = __shfl_sync(FULL, jv, s);
                    rr[u] = __ldg(&g_edata[(size_t)(cb + s) * 32 + lane]);
                    cc[u] = __ldg(&coeff_cur[jj*16 + wlo]);
                    if (MODE != 0) {
                        const float* wsp = wsum_cur + (size_t)jj * NPAD;
                        #pragma unroll
                        for (int k = 0; k < 5; k++) wsv[u][k] = __ldg(&wsp[lane + 32*k]);
                    } else {
                        #pragma unroll
                        for (int k = 0; k < 5; k++) wsv[u][k] = 0.f;
                    }
                } else {
                    rr[u] = 0.f; cc[u] = 0.f;
                    #pragma unroll
                    for (int k = 0; k < 5; k++) wsv[u][k] = 0.f;
                }
            }
            #pragma unroll
            for (int u = 0; u < 4; u++) {
                float rad = __shfl_sync(FULL, rr[u], 16 + wlo);
                float dc  = __shfl_sync(FULL, rr[u], 14);
                float rc  = rad * cc[u];
                float dcc = dc * cc[u];
                #pragma unroll
                for (int k = 0; k < 5; k++) {
                    float ang = __shfl_sync(FULL, rr[u], base + 2*k);
                    float t = acc[k];
                    if (MODE != 0) t = fmaf(dcc, wsv[u][k], t);
                    acc[k] = fmaf(ang, rc, t);
                }
            }
        }
    }

    // maintain running wsum (double-buffered); ef_orb stays in acc registers
    #pragma unroll
    for (int k = 0; k < 5; k++) {
        int idx = lane + 32*k;
        if (MODE == 0)
            g_wsum[wsel ^ 1][(size_t)a * NPAD + idx] = acc[k];
        else if (MODE == 1)
            g_wsum[wsel ^ 1][(size_t)a * NPAD + idx] = wsum_cur[(size_t)a * NPAD + idx] + acc[k];
    }
    __syncthreads();   // hyper staged

    // density: f32x2 packed. lane owns m-pairs (2lane,2lane+1) and (64+2lane,64+2lane+1).
    static const int IP[10]   = {0,1,1,1,2,2,2,2,2,2};
    static const int MULT[10] = {1,1,1,1,1,2,2,1,2,1};  // xy,xz,yz doubled
    unsigned long long hx[10][2];
    #pragma unroll
    for (int p = 0; p < 10; p++) { hx[p][0] = 0ull; hx[p][1] = 0ull; }

    #pragma unroll 4
    for (int w = 0; w < 16; w++) {
        unsigned long long Hv[3][2];
        #pragma unroll
        for (int ip = 0; ip < 3; ip++) {
            const char* hp = (const char*)(sBuf + ip * 2048 + w * 128);
            Hv[ip][0] = *(const unsigned long long*)(hp + 8*lane);
            Hv[ip][1] = *(const unsigned long long*)(hp + 256 + 8*lane);
        }
        #pragma unroll
        for (int p = 0; p < 10; p++) {
            float ev = __shfl_sync(FULL, acc[p >> 1], w + 16 * (p & 1));
            unsigned long long evp = pk2(ev, ev);
            hx[p][0] = ffma2(evp, Hv[IP[p]][0], hx[p][0]);
            hx[p][1] = ffma2(evp, Hv[IP[p]][1], hx[p][1]);
        }
    }
    unsigned long long s1[2] = {0ull, 0ull}, s2[2] = {0ull, 0ull};
    #pragma unroll
    for (int p = 0; p < 10; p++) {
        if (MULT[p] == 1) {
            s1[0] = ffma2(hx[p][0], hx[p][0], s1[0]);
            s1[1] = ffma2(hx[p][1], hx[p][1], s1[1]);
        } else {
            s2[0] = ffma2(hx[p][0], hx[p][0], s2[0]);
            s2[1] = ffma2(hx[p][1], hx[p][1], s2[1]);
        }
    }
    unsigned long long TWO = pk2(2.0f, 2.0f);
    unsigned long long ddp0 = ffma2(TWO, s2[0], s1[0]);
    unsigned long long ddp1 = ffma2(TWO, s2[1], s1[1]);

    if (MODE == 2) {
        *(unsigned long long*)(dens_out + a*128 + 2*lane)      = ddp0;
        *(unsigned long long*)(dens_out + a*128 + 64 + 2*lane) = ddp1;
        return;
    }

    __syncthreads();   // everyone done reading hyper in sBuf

    // stage W1 pair-interleaved ((h,h+32) adjacent), W2, b1 into sBuf
    for (int idx = tid; idx < 8192; idx += 256) {
        int u = idx & 63;
        sBuf[(idx & ~63) + ((u & 31) << 1) + (u >> 5)] = w1[idx];
    }
    for (int idx = tid; idx < 1024; idx += 256) sBuf[8192 + idx] = w2[idx];
    if (tid < 64) sBuf[9216 + tid] = b1[tid];
    __syncthreads();

    // MLP layer 1 (f32x2): lane computes hidden pair (lane, lane+32)
    float dd[4];
    upk2(ddp0, dd[0], dd[1]);   // m = 2*lane, 2*lane+1
    upk2(ddp1, dd[2], dd[3]);   // m = 64+2*lane, 65+2*lane
    unsigned long long hp = 0ull;
    #pragma unroll
    for (int m = 0; m < 128; m++) {
        int src = (m & 63) >> 1;
        int idx = ((m >> 6) << 1) | (m & 1);
        float d = __shfl_sync(FULL, dd[idx], src);
        unsigned long long wv = *(const unsigned long long*)((const char*)sBuf + m*256 + 8*lane);
        hp = ffma2(pk2(d, d), wv, hp);
    }
    float h0, h1;
    upk2(hp, h0, h1);
    sT[wid][lane]      = tanhf(h0 + sBuf[9216 + lane]);
    sT[wid][lane + 32] = tanhf(h1 + sBuf[9216 + lane + 32]);
    __syncwarp();
    if (lane < 16) {
        float ds = 0.f;
        #pragma unroll
        for (int hh = 0; hh < 64; hh++)
            ds = fmaf(sT[wid][hh], sBuf[8192 + hh*16 + lane], ds);
        g_coeff[csel ^ 1][a*16 + lane] = coeff_cur[a*16 + lane] + ds;
    }
}

extern "C" void kernel_launch(void* const* d_in, const int* in_sizes, int n_in,
                              void* d_out, int out_size) {
    const float* cart     = (const float*)d_in[0];
    const float* ef       = (const float*)d_in[1];
    const float* shifts   = (const float*)d_in[2];
    const float* rs       = (const float*)d_in[3];
    const float* inta     = (const float*)d_in[4];
    const float* params_p = (const float*)d_in[5];
    const float* ef_para  = (const float*)d_in[6];
    const float* hyper    = (const float*)d_in[7];
    const float* oc_w1    = (const float*)d_in[8];
    const float* oc_b1    = (const float*)d_in[9];
    const float* oc_w2    = (const float*)d_in[10];
    const int* neigh      = (const int*)d_in[11];    // JAX x64-disabled: int32
    const int* species    = (const int*)d_in[12];    // int32
    float* dens = (float*)d_out;

    k_init<<<(TOT * NW + 255) / 256, 256>>>(params_p, species, ef);
    k_count_scan<<<NE / 256, 256>>>(neigh);
    k_edge<<<NE / 256, 256>>>(cart, shifts, rs, inta, neigh, species);

    // obtain 0: coeff0 -> coeff1 (layer 0), wsum0 = ef_orb0   [4th launch -> profiled slot]
    k_obtain<0><<<TOT / 8, 256>>>(ef_para, hyper, oc_w1, oc_b1, oc_w2, dens, 0, 1);
    // obtain 1: coeff1 -> coeff0 (layer 1), wsum1 = wsum0 + ef_orb1
    k_obtain<1><<<TOT / 8, 256>>>(ef_para, hyper, oc_w1 + 8192, oc_b1 + 64, oc_w2 + 1024, dens, 1, 0);
    // obtain 2: coeff0, wsum1 -> final density to d_out
    k_obtain<2><<<TOT / 8, 256>>>(ef_para, hyper, oc_w1, oc_b1, oc_w2, dens, 0, 1);
}

// round 13
// speedup vs baseline: 1.1343x; 1.1343x over previous
#include <cuda_runtime.h>
#include <math.h>

#define TOT    8192
#define NBATCH 16
#define NE     131072
#define NW     16
#define NPAD   160     // 10 unique p * 16 w = 160 (5 regs/lane)

// ---- device-global scratch (no allocations allowed) ----
__device__ float g_edata[(size_t)NE * 32];      // CSR: [0..9]=uniq ang, [10..13]=0, [14]=dcut, [15]=0, [16..31]=radial
__device__ int   g_ej[NE];                      // CSR-ordered j index per edge
__device__ int   g_cnt[TOT];
__device__ int   g_ptr[TOT + 1];
__device__ int   g_done;                        // completion counter for count_scan (self-resetting)
__device__ float g_wsum[2][(size_t)TOT * NPAD]; // double-buffered running sum of ef_orbs (unique rows)
__device__ float g_coeff[2][TOT * NW];          // double-buffered orb_coeff
__device__ float g_angef[NBATCH * 16];          // angular(ef) unique rows, padded to 16

// ---- packed f32x2 helpers (full fp32 precision, 2 FMA/instr on sm_103a) ----
__device__ __forceinline__ unsigned long long pk2(float lo, float hi) {
    unsigned long long r;
    asm("mov.b64 %0,{%1,%2};" : "=l"(r) : "f"(lo), "f"(hi));
    return r;
}
__device__ __forceinline__ void upk2(unsigned long long v, float& lo, float& hi) {
    asm("mov.b64 {%0,%1},%2;" : "=f"(lo), "=f"(hi) : "l"(v));
}
__device__ __forceinline__ unsigned long long ffma2(unsigned long long a,
                                                    unsigned long long b,
                                                    unsigned long long c) {
    unsigned long long d;
    asm("fma.rn.f32x2 %0,%1,%2,%3;" : "=l"(d) : "l"(a), "l"(b), "l"(c));
    return d;
}

// orb_coeff init + zero CSR counters + angular(ef) unique basis
__global__ void k_init(const float* __restrict__ params_p,
                       const int* __restrict__ species,
                       const float* __restrict__ ef) {
    int t = blockIdx.x * blockDim.x + threadIdx.x;
    if (t < TOT * NW) {
        int a = t >> 4, w = t & 15;
        g_coeff[0][t] = params_p[species[a] * NW + w];
    }
    if (t < TOT) g_cnt[t] = 0;
    if (t < NBATCH) {
        float x = ef[3*t], y = ef[3*t+1], z = ef[3*t+2];
        float* o = g_angef + t * 16;
        o[0]=1.f; o[1]=x; o[2]=y; o[3]=z;
        o[4]=x*x; o[5]=x*y; o[6]=x*z; o[7]=y*y; o[8]=y*z; o[9]=z*z;
        o[10]=0.f; o[11]=0.f; o[12]=0.f; o[13]=0.f; o[14]=0.f; o[15]=0.f;
    }
}

// CSR count + (last block) exclusive scan -> g_ptr; rezero counts as cursors.
__global__ void k_count_scan(const int* __restrict__ neigh) {
    int e = blockIdx.x * blockDim.x + threadIdx.x;
    if (e < NE) atomicAdd(&g_cnt[neigh[e]], 1);
    __threadfence();
    __shared__ int isLast;
    if (threadIdx.x == 0) {
        int d = atomicAdd(&g_done, 1);
        isLast = (d == (int)gridDim.x - 1);
    }
    __syncthreads();
    if (!isLast) return;

    // last block: 256 threads x 32 counts each
    __shared__ int ss[256];
    int t = threadIdx.x;
    int loc[32]; int s = 0;
    #pragma unroll
    for (int k = 0; k < 32; k++) { loc[k] = __ldcg(&g_cnt[t*32 + k]); s += loc[k]; }
    ss[t] = s; __syncthreads();
    for (int off = 1; off < 256; off <<= 1) {
        int v = ss[t];
        int add = (t >= off) ? ss[t - off] : 0;
        __syncthreads();
        ss[t] = v + add;
        __syncthreads();
    }
    int run = ss[t] - s;
    if (t == 0) { g_ptr[0] = 0; g_done = 0; }   // reset done for next graph replay
    #pragma unroll
    for (int k = 0; k < 32; k++) {
        run += loc[k];
        g_ptr[t*32 + k + 1] = run;
        g_cnt[t*32 + k] = 0;                    // cursors for k_edge
    }
}

// per-edge geometry + radial/angular (unique rows) precompute, scattered into CSR slot
__global__ void k_edge(const float* __restrict__ cart, const float* __restrict__ shifts,
                       const float* __restrict__ rs, const float* __restrict__ inta,
                       const int* __restrict__ neigh,
                       const int* __restrict__ species) {
    int e = blockIdx.x * blockDim.x + threadIdx.x;
    if (e >= NE) return;
    int i = neigh[e];
    int j = neigh[NE + e];
    float dx = cart[3*i]   - cart[3*j]   - shifts[3*e];
    float dy = cart[3*i+1] - cart[3*j+1] - shifts[3*e+1];
    float dz = cart[3*i+2] - cart[3*j+2] - shifts[3*e+2];
    float d2 = dx*dx + dy*dy + dz*dz;
    float rinv = rsqrtf(d2);
    float d = d2 * rinv;
    float ux = dx * rinv, uy = dy * rinv, uz = dz * rinv;
    float fc = 0.5f * __cosf(d * 0.6283185307179586f) + 0.5f;
    float dcut = fc * fc;
    int sp = species[j];

    float buf[32];
    // unique angular rows: 0:1, 1:x,2:y,3:z, 4:xx,5:xy,6:xz,7:yy,8:yz,9:zz (all * dcut)
    buf[0] = dcut;
    buf[1] = dcut*ux; buf[2] = dcut*uy; buf[3] = dcut*uz;
    buf[4] = buf[1]*ux; buf[5] = buf[1]*uy; buf[6] = buf[1]*uz;
    buf[7] = buf[2]*uy; buf[8] = buf[2]*uz; buf[9] = buf[3]*uz;
    buf[10]=0.f; buf[11]=0.f; buf[12]=0.f; buf[13]=0.f;
    buf[14]=dcut; buf[15]=0.f;
    #pragma unroll
    for (int w = 0; w < 16; w++) {
        float t = d - rs[sp*16 + w];
        buf[16 + w] = __expf(inta[sp*16 + w] * t * t);
    }
    int pos = g_ptr[i] + atomicAdd(&g_cnt[i], 1);   // CSR slot
    float4* dst = (float4*)(g_edata + (size_t)pos * 32);
    const float4* src = (const float4*)buf;
    #pragma unroll
    for (int q = 0; q < 8; q++) dst[q] = src[q];
    g_ej[pos] = j;
}

// Fused obtain: gather (warp-per-atom, 4 independent edge streams for ILP)
//               -> density (f32x2) -> wsum update -> MLP (f32x2).
// MODE 0: first obtain (no wsum term; wsum_next = ef_orb; MLP)
// MODE 1: middle obtain (wsum term; wsum_next = wsum_cur + ef_orb; MLP)
// MODE 2: last obtain (wsum term; density -> d_out; no wsum/MLP)
// Lane map: idx = lane + 32k (k<5): w = lane&15, pu = (lane>>4) + 2k  (pu in 0..9).
// Owner of (pu,w): lane = w + 16*(pu&1), register acc[pu>>1].
template<int MODE>
__global__ void __launch_bounds__(256, 3) k_obtain(
    const float* __restrict__ ef_para, const float* __restrict__ hyper,
    const float* __restrict__ w1, const float* __restrict__ b1,
    const float* __restrict__ w2, float* __restrict__ dens_out,
    int csel, int wsel)
{
    __shared__ float sBuf[9280];   // [0:6144) hyper; reused: W1(pair-interleaved)[0:8192) W2[8192:9216) b1[9216:9280)
    __shared__ float sT[8][64];    // tanh staging per warp
    const unsigned FULL = 0xFFFFFFFFu;
    int tid = threadIdx.x, lane = tid & 31, wid = tid >> 5;
    int a = blockIdx.x * 8 + wid;

    const float* coeff_cur = g_coeff[csel];
    const float* wsum_cur  = g_wsum[wsel];

    // stage hyper early (float4); latency hides behind gather
    for (int idx = tid; idx < 1536; idx += 256)
        ((float4*)sBuf)[idx] = ((const float4*)hyper)[idx];

    int wlo = lane & 15;
    int base = lane >> 4;
    int b = a >> 9;                    // batch = atom / 512
    float efw = ef_para[wlo];

    // 4 independent accumulator streams (ILP); stream 0 carries ef_orb0 init
    float av[4][5];
    #pragma unroll
    for (int u = 0; u < 4; u++)
        #pragma unroll
        for (int k = 0; k < 5; k++) av[u][k] = 0.f;
    #pragma unroll
    for (int k = 0; k < 5; k++)
        av[0][k] = g_angef[b*16 + base + 2*k] * efw;   // ef_orb0 unique rows

    int start = g_ptr[a], end = g_ptr[a + 1];
    for (int cb = start; cb < end; cb += 32) {
        int cn = min(32, end - cb);
        int jv = (cb + lane < end) ? __ldg(&g_ej[cb + lane]) : 0;
        int Q = (cn + 3) >> 2;         // quarter length
        for (int q = 0; q < Q; q++) {
            float rr[4], cc[4], wsv[4][5];
            #pragma unroll
            for (int u = 0; u < 4; u++) {
                int s = q + u * Q;
                if (s < cn) {                           // warp-uniform guard
                    int jj = __shfl_sync(FULL, jv, s);
                    rr[u] = __ldg(&g_edata[(size_t)(cb + s) * 32 + lane]);
                    cc[u] = __ldg(&coeff_cur[jj*16 + wlo]);
                    if (MODE != 0) {
                        const float* wsp = wsum_cur + (size_t)jj * NPAD;
                        #pragma unroll
                        for (int k = 0; k < 5; k++) wsv[u][k] = __ldg(&wsp[lane + 32*k]);
                    } else {
                        #pragma unroll
                        for (int k = 0; k < 5; k++) wsv[u][k] = 0.f;
                    }
                } else {
                    rr[u] = 0.f; cc[u] = 0.f;
                    #pragma unroll
                    for (int k = 0; k < 5; k++) wsv[u][k] = 0.f;
                }
            }
            #pragma unroll
            for (int u = 0; u < 4; u++) {
                float rad = __shfl_sync(FULL, rr[u], 16 + wlo);
                float dc  = __shfl_sync(FULL, rr[u], 14);
                float rc  = rad * cc[u];
                float dcc = dc * cc[u];
                #pragma unroll
                for (int k = 0; k < 5; k++) {
                    float ang = __shfl_sync(FULL, rr[u], base + 2*k);
                    float t = av[u][k];
                    if (MODE != 0) t = fmaf(dcc, wsv[u][k], t);
                    av[u][k] = fmaf(ang, rc, t);
                }
            }
        }
    }
    // reduce the 4 streams
    float acc[5];
    #pragma unroll
    for (int k = 0; k < 5; k++)
        acc[k] = (av[0][k] + av[1][k]) + (av[2][k] + av[3][k]);

    // maintain running wsum (double-buffered); ef_orb stays in acc registers
    #pragma unroll
    for (int k = 0; k < 5; k++) {
        int idx = lane + 32*k;
        if (MODE == 0)
            g_wsum[wsel ^ 1][(size_t)a * NPAD + idx] = acc[k];
        else if (MODE == 1)
            g_wsum[wsel ^ 1][(size_t)a * NPAD + idx] = wsum_cur[(size_t)a * NPAD + idx] + acc[k];
    }
    __syncthreads();   // hyper staged

    // density: f32x2 packed. lane owns m-pairs (2lane,2lane+1) and (64+2lane,64+2lane+1).
    static const int IP[10]   = {0,1,1,1,2,2,2,2,2,2};
    static const int MULT[10] = {1,1,1,1,1,2,2,1,2,1};  // xy,xz,yz doubled
    unsigned long long hx[10][2];
    #pragma unroll
    for (int p = 0; p < 10; p++) { hx[p][0] = 0ull; hx[p][1] = 0ull; }

    #pragma unroll 4
    for (int w = 0; w < 16; w++) {
        unsigned long long Hv[3][2];
        #pragma unroll
        for (int ip = 0; ip < 3; ip++) {
            const char* hp = (const char*)(sBuf + ip * 2048 + w * 128);
            Hv[ip][0] = *(const unsigned long long*)(hp + 8*lane);
            Hv[ip][1] = *(const unsigned long long*)(hp + 256 + 8*lane);
        }
        #pragma unroll
        for (int p = 0; p < 10; p++) {
            float ev = __shfl_sync(FULL, acc[p >> 1], w + 16 * (p & 1));
            unsigned long long evp = pk2(ev, ev);
            hx[p][0] = ffma2(evp, Hv[IP[p]][0], hx[p][0]);
            hx[p][1] = ffma2(evp, Hv[IP[p]][1], hx[p][1]);
        }
    }
    unsigned long long s1[2] = {0ull, 0ull}, s2[2] = {0ull, 0ull};
    #pragma unroll
    for (int p = 0; p < 10; p++) {
        if (MULT[p] == 1) {
            s1[0] = ffma2(hx[p][0], hx[p][0], s1[0]);
            s1[1] = ffma2(hx[p][1], hx[p][1], s1[1]);
        } else {
            s2[0] = ffma2(hx[p][0], hx[p][0], s2[0]);
            s2[1] = ffma2(hx[p][1], hx[p][1], s2[1]);
        }
    }
    unsigned long long TWO = pk2(2.0f, 2.0f);
    unsigned long long ddp0 = ffma2(TWO, s2[0], s1[0]);
    unsigned long long ddp1 = ffma2(TWO, s2[1], s1[1]);

    if (MODE == 2) {
        *(unsigned long long*)(dens_out + a*128 + 2*lane)      = ddp0;
        *(unsigned long long*)(dens_out + a*128 + 64 + 2*lane) = ddp1;
        return;
    }

    __syncthreads();   // everyone done reading hyper in sBuf

    // stage W1 pair-interleaved ((h,h+32) adjacent), W2, b1 into sBuf
    for (int idx = tid; idx < 8192; idx += 256) {
        int u = idx & 63;
        sBuf[(idx & ~63) + ((u & 31) << 1) + (u >> 5)] = w1[idx];
    }
    for (int idx = tid; idx < 1024; idx += 256) sBuf[8192 + idx] = w2[idx];
    if (tid < 64) sBuf[9216 + tid] = b1[tid];
    __syncthreads();

    // MLP layer 1 (f32x2): lane computes hidden pair (lane, lane+32)
    float dd[4];
    upk2(ddp0, dd[0], dd[1]);   // m = 2*lane, 2*lane+1
    upk2(ddp1, dd[2], dd[3]);   // m = 64+2*lane, 65+2*lane
    unsigned long long hp = 0ull;
    #pragma unroll
    for (int m = 0; m < 128; m++) {
        int src = (m & 63) >> 1;
        int idx = ((m >> 6) << 1) | (m & 1);
        float d = __shfl_sync(FULL, dd[idx], src);
        unsigned long long wv = *(const unsigned long long*)((const char*)sBuf + m*256 + 8*lane);
        hp = ffma2(pk2(d, d), wv, hp);
    }
    float h0, h1;
    upk2(hp, h0, h1);
    sT[wid][lane]      = tanhf(h0 + sBuf[9216 + lane]);
    sT[wid][lane + 32] = tanhf(h1 + sBuf[9216 + lane + 32]);
    __syncwarp();
    if (lane < 16) {
        float ds = 0.f;
        #pragma unroll
        for (int hh = 0; hh < 64; hh++)
            ds = fmaf(sT[wid][hh], sBuf[8192 + hh*16 + lane], ds);
        g_coeff[csel ^ 1][a*16 + lane] = coeff_cur[a*16 + lane] + ds;
    }
}

extern "C" void kernel_launch(void* const* d_in, const int* in_sizes, int n_in,
                              void* d_out, int out_size) {
    const float* cart     = (const float*)d_in[0];
    const float* ef       = (const float*)d_in[1];
    const float* shifts   = (const float*)d_in[2];
    const float* rs       = (const float*)d_in[3];
    const float* inta     = (const float*)d_in[4];
    const float* params_p = (const float*)d_in[5];
    const float* ef_para  = (const float*)d_in[6];
    const float* hyper    = (const float*)d_in[7];
    const float* oc_w1    = (const float*)d_in[8];
    const float* oc_b1    = (const float*)d_in[9];
    const float* oc_w2    = (const float*)d_in[10];
    const int* neigh      = (const int*)d_in[11];    // JAX x64-disabled: int32
    const int* species    = (const int*)d_in[12];    // int32
    float* dens = (float*)d_out;

    k_init<<<(TOT * NW + 255) / 256, 256>>>(params_p, species, ef);
    k_count_scan<<<NE / 256, 256>>>(neigh);
    k_edge<<<NE / 256, 256>>>(cart, shifts, rs, inta, neigh, species);

    // obtain 0: coeff0 -> coeff1 (layer 0), wsum0 = ef_orb0   [profiled slot]
    k_obtain<0><<<TOT / 8, 256>>>(ef_para, hyper, oc_w1, oc_b1, oc_w2, dens, 0, 1);
    // obtain 1: coeff1 -> coeff0 (layer 1), wsum1 = wsum0 + ef_orb1
    k_obtain<1><<<TOT / 8, 256>>>(ef_para, hyper, oc_w1 + 8192, oc_b1 + 64, oc_w2 + 1024, dens, 1, 0);
    // obtain 2: coeff0, wsum1 -> final density to d_out
    k_obtain<2><<<TOT / 8, 256>>>(ef_para, hyper, oc_w1, oc_b1, oc_w2, dens, 0, 1);
}

// round 15
// speedup vs baseline: 1.1350x; 1.0007x over previous
#include <cuda_runtime.h>
#include <math.h>

#define TOT    8192
#define NBATCH 16
#define NE     131072
#define NW     16
#define NPAD   160     // 10 unique p * 16 w = 160 (5 regs/lane)

// ---- device-global scratch (no allocations allowed) ----
__device__ float g_edata[(size_t)NE * 32];      // CSR: [0..9]=uniq ang, [10..13]=0, [14]=dcut, [15]=0, [16..31]=radial
__device__ int   g_ej[NE];                      // CSR-ordered j index per edge
__device__ int   g_cnt[TOT];
__device__ int   g_ptr[TOT + 1];
__device__ int   g_done;                        // completion counter for count_scan (self-resetting)
__device__ float g_eforb[(size_t)TOT * NPAD];   // ef_orb of current obtain (gather -> dens)
__device__ float g_wsum[2][(size_t)TOT * NPAD]; // double-buffered running sum of ef_orbs
__device__ float g_coeff[2][TOT * NW];          // double-buffered orb_coeff
__device__ float g_angef[NBATCH * 16];          // angular(ef) unique rows, padded to 16

// ---- packed f32x2 helpers (full fp32 precision, 2 FMA/instr on sm_103a) ----
__device__ __forceinline__ unsigned long long pk2(float lo, float hi) {
    unsigned long long r;
    asm("mov.b64 %0,{%1,%2};" : "=l"(r) : "f"(lo), "f"(hi));
    return r;
}
__device__ __forceinline__ void upk2(unsigned long long v, float& lo, float& hi) {
    asm("mov.b64 {%0,%1},%2;" : "=f"(lo), "=f"(hi) : "l"(v));
}
__device__ __forceinline__ unsigned long long ffma2(unsigned long long a,
                                                    unsigned long long b,
                                                    unsigned long long c) {
    unsigned long long d;
    asm("fma.rn.f32x2 %0,%1,%2,%3;" : "=l"(d) : "l"(a), "l"(b), "l"(c));
    return d;
}
__device__ __forceinline__ unsigned long long fadd2(unsigned long long a,
                                                    unsigned long long b) {
    unsigned long long d;
    asm("add.rn.f32x2 %0,%1,%2;" : "=l"(d) : "l"(a), "l"(b));
    return d;
}

// orb_coeff init + zero CSR counters + angular(ef) unique basis
__global__ void k_init(const float* __restrict__ params_p,
                       const int* __restrict__ species,
                       const float* __restrict__ ef) {
    int t = blockIdx.x * blockDim.x + threadIdx.x;
    if (t < TOT * NW) {
        int a = t >> 4, w = t & 15;
        g_coeff[0][t] = params_p[species[a] * NW + w];
    }
    if (t < TOT) g_cnt[t] = 0;
    if (t < NBATCH) {
        float x = ef[3*t], y = ef[3*t+1], z = ef[3*t+2];
        float* o = g_angef + t * 16;
        o[0]=1.f; o[1]=x; o[2]=y; o[3]=z;
        o[4]=x*x; o[5]=x*y; o[6]=x*z; o[7]=y*y; o[8]=y*z; o[9]=z*z;
        o[10]=0.f; o[11]=0.f; o[12]=0.f; o[13]=0.f; o[14]=0.f; o[15]=0.f;
    }
}

// CSR count + (last block) exclusive scan -> g_ptr; rezero counts as cursors.
__global__ void k_count_scan(const int* __restrict__ neigh) {
    int e = blockIdx.x * blockDim.x + threadIdx.x;
    if (e < NE) atomicAdd(&g_cnt[neigh[e]], 1);
    __threadfence();
    __shared__ int isLast;
    if (threadIdx.x == 0) {
        int d = atomicAdd(&g_done, 1);
        isLast = (d == (int)gridDim.x - 1);
    }
    __syncthreads();
    if (!isLast) return;

    __shared__ int ss[256];
    int t = threadIdx.x;
    int loc[32]; int s = 0;
    #pragma unroll
    for (int k = 0; k < 32; k++) { loc[k] = __ldcg(&g_cnt[t*32 + k]); s += loc[k]; }
    ss[t] = s; __syncthreads();
    for (int off = 1; off < 256; off <<= 1) {
        int v = ss[t];
        int add = (t >= off) ? ss[t - off] : 0;
        __syncthreads();
        ss[t] = v + add;
        __syncthreads();
    }
    int run = ss[t] - s;
    if (t == 0) { g_ptr[0] = 0; g_done = 0; }
    #pragma unroll
    for (int k = 0; k < 32; k++) {
        run += loc[k];
        g_ptr[t*32 + k + 1] = run;
        g_cnt[t*32 + k] = 0;
    }
}

// per-edge geometry + radial/angular (unique rows) precompute, scattered into CSR slot
__global__ void k_edge(const float* __restrict__ cart, const float* __restrict__ shifts,
                       const float* __restrict__ rs, const float* __restrict__ inta,
                       const int* __restrict__ neigh,
                       const int* __restrict__ species) {
    __shared__ float s_rs[64], s_inta[64];
    if (threadIdx.x < 64)       s_rs[threadIdx.x]   = rs[threadIdx.x];
    else if (threadIdx.x < 128) s_inta[threadIdx.x - 64] = inta[threadIdx.x - 64];
    __syncthreads();

    int e = blockIdx.x * blockDim.x + threadIdx.x;
    if (e >= NE) return;
    int i = neigh[e];
    int j = neigh[NE + e];
    float dx = cart[3*i]   - cart[3*j]   - shifts[3*e];
    float dy = cart[3*i+1] - cart[3*j+1] - shifts[3*e+1];
    float dz = cart[3*i+2] - cart[3*j+2] - shifts[3*e+2];
    float d2 = dx*dx + dy*dy + dz*dz;
    float rinv = rsqrtf(d2);
    float d = d2 * rinv;
    float ux = dx * rinv, uy = dy * rinv, uz = dz * rinv;
    float fc = 0.5f * __cosf(d * 0.6283185307179586f) + 0.5f;
    float dcut = fc * fc;
    int sp = species[j];

    float buf[32];
    buf[0] = dcut;
    buf[1] = dcut*ux; buf[2] = dcut*uy; buf[3] = dcut*uz;
    buf[4] = buf[1]*ux; buf[5] = buf[1]*uy; buf[6] = buf[1]*uz;
    buf[7] = buf[2]*uy; buf[8] = buf[2]*uz; buf[9] = buf[3]*uz;
    buf[10]=0.f; buf[11]=0.f; buf[12]=0.f; buf[13]=0.f;
    buf[14]=dcut; buf[15]=0.f;
    #pragma unroll
    for (int w = 0; w < 16; w++) {
        float t = d - s_rs[sp*16 + w];
        buf[16 + w] = __expf(s_inta[sp*16 + w] * t * t);
    }
    int pos = g_ptr[i] + atomicAdd(&g_cnt[i], 1);
    float4* dst = (float4*)(g_edata + (size_t)pos * 32);
    const float4* src = (const float4*)buf;
    #pragma unroll
    for (int q = 0; q < 8; q++) dst[q] = src[q];
    g_ej[pos] = j;
}

// Gather kernel: warp-per-atom, 4 independent edge streams, NO shared memory
// (high occupancy for latency hiding). Writes ef_orb to g_eforb + wsum update.
// MODE 0: no wsum term; wsum_next = ef_orb
// MODE 1: wsum term;    wsum_next = wsum_cur + ef_orb
// MODE 2: wsum term;    no wsum write
// Lane map: idx = lane + 32k (k<5): w = lane&15, pu = (lane>>4) + 2k.
template<int MODE>
__global__ void k_gather(const float* __restrict__ ef_para, int csel, int wsel) {
    const unsigned FULL = 0xFFFFFFFFu;
    int lane = threadIdx.x & 31, wid = threadIdx.x >> 5;
    int a = blockIdx.x * 8 + wid;

    const float* coeff_cur = g_coeff[csel];
    const float* wsum_cur  = g_wsum[wsel];

    int wlo = lane & 15;
    int base = lane >> 4;
    int b = a >> 9;
    float efw = ef_para[wlo];

    float av[4][5];
    #pragma unroll
    for (int u = 0; u < 4; u++)
        #pragma unroll
        for (int k = 0; k < 5; k++) av[u][k] = 0.f;
    #pragma unroll
    for (int k = 0; k < 5; k++)
        av[0][k] = g_angef[b*16 + base + 2*k] * efw;   // ef_orb0 unique rows

    int start = g_ptr[a], end = g_ptr[a + 1];
    for (int cb = start; cb < end; cb += 32) {
        int cn = min(32, end - cb);
        int jv = (cb + lane < end) ? __ldg(&g_ej[cb + lane]) : 0;
        int Q = (cn + 3) >> 2;
        for (int q = 0; q < Q; q++) {
            float rr[4], cc[4], wsv[4][5];
            #pragma unroll
            for (int u = 0; u < 4; u++) {
                int s = q + u * Q;
                if (s < cn) {                           // warp-uniform guard
                    int jj = __shfl_sync(FULL, jv, s);
                    rr[u] = __ldg(&g_edata[(size_t)(cb + s) * 32 + lane]);
                    cc[u] = __ldg(&coeff_cur[jj*16 + wlo]);
                    if (MODE != 0) {
                        const float* wsp = wsum_cur + (size_t)jj * NPAD;
                        #pragma unroll
                        for (int k = 0; k < 5; k++) wsv[u][k] = __ldg(&wsp[lane + 32*k]);
                    } else {
                        #pragma unroll
                        for (int k = 0; k < 5; k++) wsv[u][k] = 0.f;
                    }
                } else {
                    rr[u] = 0.f; cc[u] = 0.f;
                    #pragma unroll
                    for (int k = 0; k < 5; k++) wsv[u][k] = 0.f;
                }
            }
            #pragma unroll
            for (int u = 0; u < 4; u++) {
                float rad = __shfl_sync(FULL, rr[u], 16 + wlo);
                float dc  = __shfl_sync(FULL, rr[u], 14);
                float rc  = rad * cc[u];
                float dcc = dc * cc[u];
                #pragma unroll
                for (int k = 0; k < 5; k++) {
                    float ang = __shfl_sync(FULL, rr[u], base + 2*k);
                    float t = av[u][k];
                    if (MODE != 0) t = fmaf(dcc, wsv[u][k], t);
                    av[u][k] = fmaf(ang, rc, t);
                }
            }
        }
    }

    #pragma unroll
    for (int k = 0; k < 5; k++) {
        int idx = lane + 32*k;
        float acc = (av[0][k] + av[1][k]) + (av[2][k] + av[3][k]);
        g_eforb[(size_t)a * NPAD + idx] = acc;
        if (MODE == 0)
            g_wsum[wsel ^ 1][(size_t)a * NPAD + idx] = acc;
        else if (MODE == 1)
            g_wsum[wsel ^ 1][(size_t)a * NPAD + idx] = wsum_cur[(size_t)a * NPAD + idx] + acc;
    }
}

// Density (+ MLP unless LAST) kernel: warp-per-atom, uniform work.
// density: f32x2 packed; lane owns m-pairs (2lane,2lane+1),(64+2lane,65+2lane).
template<int LAST>
__global__ void __launch_bounds__(256, 3) k_dens(
    const float* __restrict__ hyper,
    const float* __restrict__ w1, const float* __restrict__ b1,
    const float* __restrict__ w2, float* __restrict__ dens_out, int csel)
{
    __shared__ float sBuf[9280];   // [0:6144) hyper; reused: W1(pair-interleaved)[0:8192) W2[8192:9216) b1[9216:9280)
    __shared__ float sT[8][64];
    const unsigned FULL = 0xFFFFFFFFu;
    int tid = threadIdx.x, lane = tid & 31, wid = tid >> 5;
    int a = blockIdx.x * 8 + wid;

    for (int idx = tid; idx < 1536; idx += 256)
        ((float4*)sBuf)[idx] = ((const float4*)hyper)[idx];

    float acc[5];
    #pragma unroll
    for (int k = 0; k < 5; k++)
        acc[k] = g_eforb[(size_t)a * NPAD + lane + 32*k];
    __syncthreads();   // hyper staged

    static const int IP[10]   = {0,1,1,1,2,2,2,2,2,2};
    static const int MULT[10] = {1,1,1,1,1,2,2,1,2,1};  // xy,xz,yz doubled
    unsigned long long hx[10][2];
    #pragma unroll
    for (int p = 0; p < 10; p++) { hx[p][0] = 0ull; hx[p][1] = 0ull; }

    #pragma unroll 4
    for (int w = 0; w < 16; w++) {
        unsigned long long Hv[3][2];
        #pragma unroll
        for (int ip = 0; ip < 3; ip++) {
            const char* hp = (const char*)(sBuf + ip * 2048 + w * 128);
            Hv[ip][0] = *(const unsigned long long*)(hp + 8*lane);
            Hv[ip][1] = *(const unsigned long long*)(hp + 256 + 8*lane);
        }
        #pragma unroll
        for (int p = 0; p < 10; p++) {
            float ev = __shfl_sync(FULL, acc[p >> 1], w + 16 * (p & 1));
            unsigned long long evp = pk2(ev, ev);
            hx[p][0] = ffma2(evp, Hv[IP[p]][0], hx[p][0]);
            hx[p][1] = ffma2(evp, Hv[IP[p]][1], hx[p][1]);
        }
    }
    unsigned long long s1[2] = {0ull, 0ull}, s2[2] = {0ull, 0ull};
    #pragma unroll
    for (int p = 0; p < 10; p++) {
        if (MULT[p] == 1) {
            s1[0] = ffma2(hx[p][0], hx[p][0], s1[0]);
            s1[1] = ffma2(hx[p][1], hx[p][1], s1[1]);
        } else {
            s2[0] = ffma2(hx[p][0], hx[p][0], s2[0]);
            s2[1] = ffma2(hx[p][1], hx[p][1], s2[1]);
        }
    }
    unsigned long long TWO = pk2(2.0f, 2.0f);
    unsigned long long ddp0 = ffma2(TWO, s2[0], s1[0]);
    unsigned long long ddp1 = ffma2(TWO, s2[1], s1[1]);

    if (LAST) {
        *(unsigned long long*)(dens_out + a*128 + 2*lane)      = ddp0;
        *(unsigned long long*)(dens_out + a*128 + 64 + 2*lane) = ddp1;
        return;
    }

    __syncthreads();   // everyone done reading hyper

    for (int idx = tid; idx < 8192; idx += 256) {
        int u = idx & 63;
        sBuf[(idx & ~63) + ((u & 31) << 1) + (u >> 5)] = w1[idx];
    }
    for (int idx = tid; idx < 1024; idx += 256) sBuf[8192 + idx] = w2[idx];
    if (tid < 64) sBuf[9216 + tid] = b1[tid];
    __syncthreads();

    // MLP layer 1 (f32x2): 4 independent accumulator chains
    float dd[4];
    upk2(ddp0, dd[0], dd[1]);
    upk2(ddp1, dd[2], dd[3]);
    unsigned long long hp[4] = {0ull, 0ull, 0ull, 0ull};
    #pragma unroll
    for (int m = 0; m < 128; m++) {
        int src = (m & 63) >> 1;
        int idx = ((m >> 6) << 1) | (m & 1);
        float d = __shfl_sync(FULL, dd[idx], src);
        unsigned long long wv = *(const unsigned long long*)((const char*)sBuf + m*256 + 8*lane);
        hp[m & 3] = ffma2(pk2(d, d), wv, hp[m & 3]);
    }
    unsigned long long hsum = fadd2(fadd2(hp[0], hp[1]), fadd2(hp[2], hp[3]));
    float h0, h1;
    upk2(hsum, h0, h1);
    sT[wid][lane]      = tanhf(h0 + sBuf[9216 + lane]);
    sT[wid][lane + 32] = tanhf(h1 + sBuf[9216 + lane + 32]);
    __syncwarp();
    if (lane < 16) {
        float ds = 0.f;
        #pragma unroll
        for (int hh = 0; hh < 64; hh++)
            ds = fmaf(sT[wid][hh], sBuf[8192 + hh*16 + lane], ds);
        g_coeff[csel ^ 1][a*16 + lane] = g_coeff[csel][a*16 + lane] + ds;
    }
}

extern "C" void kernel_launch(void* const* d_in, const int* in_sizes, int n_in,
                              void* d_out, int out_size) {
    const float* cart     = (const float*)d_in[0];
    const float* ef       = (const float*)d_in[1];
    const float* shifts   = (const float*)d_in[2];
    const float* rs       = (const float*)d_in[3];
    const float* inta     = (const float*)d_in[4];
    const float* params_p = (const float*)d_in[5];
    const float* ef_para  = (const float*)d_in[6];
    const float* hyper    = (const float*)d_in[7];
    const float* oc_w1    = (const float*)d_in[8];
    const float* oc_b1    = (const float*)d_in[9];
    const float* oc_w2    = (const float*)d_in[10];
    const int* neigh      = (const int*)d_in[11];    // JAX x64-disabled: int32
    const int* species    = (const int*)d_in[12];    // int32
    float* dens = (float*)d_out;

    k_init<<<(TOT * NW + 255) / 256, 256>>>(params_p, species, ef);
    k_count_scan<<<NE / 256, 256>>>(neigh);
    k_edge<<<NE / 256, 256>>>(cart, shifts, rs, inta, neigh, species);

    // obtain 0: coeff0 -> coeff1 (layer 0), wsum0 = ef_orb0   [k_gather<0> in profiled slot]
    k_gather<0><<<TOT / 8, 256>>>(ef_para, 0, 1);
    k_dens<0><<<TOT / 8, 256>>>(hyper, oc_w1, oc_b1, oc_w2, dens, 0);
    // obtain 1: coeff1 -> coeff0 (layer 1), wsum1 = wsum0 + ef_orb1
    k_gather<1><<<TOT / 8, 256>>>(ef_para, 1, 0);
    k_dens<0><<<TOT / 8, 256>>>(hyper, oc_w1 + 8192, oc_b1 + 64, oc_w2 + 1024, dens, 1);
    // obtain 2: coeff0, wsum1 -> final density to d_out
    k_gather<2><<<TOT / 8, 256>>>(ef_para, 0, 1);
    k_dens<1><<<TOT / 8, 256>>>(hyper, oc_w1, oc_b1, oc_w2, dens, 0);
}